// round 6
// baseline (speedup 1.0000x reference)
#include <cuda_runtime.h>
#include <cstdint>

#define SEQ   4096
#define EMB   1024
#define NH    16
#define HD    64
#define WIN   256
#define QKV_N 3072
#define NT64  (SEQ / 64)

// ---- GEMM tiling: 128x128x32, 8 warps (2x4), warp tile 64x32 ----
#define STG 3
#define STAGE_F 8192                 // floats per stage: A 4096 + B 4096
#define GEMM_SMEM (STG * STAGE_F * 4)

// ---- attention P-buffer stride ----
#define LQ 68

static __device__ float g_qkv[SEQ * QKV_N];        // fp32 q|k|v (GEMM1 out)
static __device__ float g_ctx[SEQ * EMB];          // attention out (plain fp32)
static __device__ float g_xap[SEQ * EMB];          // x, A-frag packed, tf32
static __device__ float g_cxp[SEQ * EMB];          // ctx, A-frag packed, tf32
static __device__ float g_wqp[EMB * QKV_N];        // w_qkv, B-frag packed, tf32
static __device__ float g_wop[EMB * EMB];          // w_out, B-frag packed, tf32
static __device__ float g_qpk[NH * NT64 * 4096];   // Q frag-packed per (head, tile)
static __device__ float g_kpk[NH * NT64 * 4096];   // K frag-packed
static __device__ float g_vpk[NH * NT64 * 4096];   // V frag-packed

// ===========================================================================
__device__ __forceinline__ uint32_t f2tf(float x) {
    uint32_t r;
    asm("cvt.rna.tf32.f32 %0, %1;" : "=r"(r) : "f"(x));
    return r;
}
__device__ __forceinline__ float tfr(float x) { return __uint_as_float(f2tf(x)); }

__device__ __forceinline__ void mma_tf32(float d[4], const uint32_t a[4], const uint32_t b[2]) {
    asm volatile(
        "mma.sync.aligned.m16n8k8.row.col.f32.tf32.tf32.f32 "
        "{%0,%1,%2,%3}, {%4,%5,%6,%7}, {%8,%9}, {%0,%1,%2,%3};\n"
        : "+f"(d[0]), "+f"(d[1]), "+f"(d[2]), "+f"(d[3])
        : "r"(a[0]), "r"(a[1]), "r"(a[2]), "r"(a[3]), "r"(b[0]), "r"(b[1]));
}
__device__ __forceinline__ void cp16(float* smem_dst, const float* gsrc) {
    uint32_t saddr;
    asm("{ .reg .u64 t; cvta.to.shared.u64 t, %1; cvt.u32.u64 %0, t; }" : "=r"(saddr) : "l"(smem_dst));
    asm volatile("cp.async.cg.shared.global [%0], [%1], 16;\n" :: "r"(saddr), "l"(gsrc) : "memory");
}

// ===========================================================================
// pack_a: S[M,K] fp32 -> A-frag-packed tf32. Block=(kt, by).
// Layout per (by,kt) tile (4096 floats): [wm][ks][mi][lane] float4,
// float4 = { S[r][c], S[r+8][c], S[r][c+4], S[r+8][c+4] },
// r = by*128 + wm*64 + mi*16 + lr, c = kt*32 + ks*8 + lc.
// ===========================================================================
__global__ __launch_bounds__(256) void pack_a(const float* __restrict__ S,
                                              float* __restrict__ D, int K) {
    const int kt = blockIdx.x, by = blockIdx.y, t = threadIdx.x;
    const int KT = K >> 5;
    float4* out = (float4*)(D + ((size_t)(by * KT + kt)) * 4096);
#pragma unroll
    for (int i = 0; i < 4; i++) {
        int o = t + 256 * i;
        int lane = o & 31, mi = (o >> 5) & 3, ks = (o >> 7) & 3, wm = (o >> 9) & 1;
        int lr = lane >> 2, lc = lane & 3;
        int row = by * 128 + wm * 64 + mi * 16 + lr;
        int col = kt * 32 + ks * 8 + lc;
        const float* s = S + (size_t)row * K + col;
        float4 v;
        v.x = tfr(s[0]);
        v.y = tfr(s[(size_t)8 * K]);
        v.z = tfr(s[4]);
        v.w = tfr(s[(size_t)8 * K + 4]);
        out[o] = v;
    }
}

// ===========================================================================
// pack_b: W[K,N] fp32 -> B-frag-packed tf32. Block=(kt, bx).
// Layout per (bx,kt) tile: [wn][ks][half][lane] float4,
// float4 = { W[k][n], W[k+4][n], W[k][n+8], W[k+4][n+8] },
// k = kt*32 + ks*8 + lc, n = bx*128 + wn*32 + half*16 + lr.
// ===========================================================================
__global__ __launch_bounds__(256) void pack_b(const float* __restrict__ W,
                                              float* __restrict__ D, int K, int N) {
    const int kt = blockIdx.x, bx = blockIdx.y, t = threadIdx.x;
    const int KT = K >> 5;
    float4* out = (float4*)(D + ((size_t)(bx * KT + kt)) * 4096);
#pragma unroll
    for (int i = 0; i < 4; i++) {
        int o = t + 256 * i;
        int lane = o & 31, half = (o >> 5) & 1, ks = (o >> 6) & 3, wn = (o >> 8) & 3;
        int lr = lane >> 2, lc = lane & 3;
        int k = kt * 32 + ks * 8 + lc;
        int n = bx * 128 + wn * 32 + half * 16 + lr;
        const float* s = W + (size_t)k * N + n;
        float4 v;
        v.x = tfr(s[0]);
        v.y = tfr(s[(size_t)4 * N]);
        v.z = tfr(s[8]);
        v.w = tfr(s[(size_t)4 * N + 8]);
        out[o] = v;
    }
}

// ===========================================================================
// pack_qkv: qkv[S,3E] fp32 -> Q/K/V frag-packed tf32 per (head, 64-tile).
// Q: [w][ks][lane] f4 = {Q[r][c], Q[r+8][c], Q[r][c+4], Q[r+8][c+4]},
//    r = tile*64 + w*16 + lr, c(head-local) = ks*8 + lc.
// K: [ks][pr][lane] f4 = {K[key][d], K[key][d+4], K[key+8][d], K[key+8][d+4]},
//    key = tile*64 + pr*16 + lr, d = ks*8 + lc.
// V: [ks][pr][lane] f4 = {V[vr][vd], V[vr+4][vd], V[vr][vd+8], V[vr+4][vd+8]},
//    vr(key) = tile*64 + ks*8 + lc, vd(dim) = pr*16 + lr.
// ===========================================================================
__global__ __launch_bounds__(256) void pack_qkv(const float* __restrict__ qkv,
                                                float* __restrict__ Qp,
                                                float* __restrict__ Kp,
                                                float* __restrict__ Vp) {
    const int tile = blockIdx.x, h = blockIdx.y, t = threadIdx.x;
    const size_t base = ((size_t)(h * NT64 + tile)) * 4096;
    float4* qo = (float4*)(Qp + base);
    float4* ko = (float4*)(Kp + base);
    float4* vo = (float4*)(Vp + base);
#pragma unroll
    for (int i = 0; i < 4; i++) {
        int o = t + 256 * i;
        int lane = o & 31;
        int lr = lane >> 2, lc = lane & 3;
        // Q
        {
            int ks = (o >> 5) & 7, w = (o >> 8) & 3;
            int row = tile * 64 + w * 16 + lr;
            int col = h * 64 + ks * 8 + lc;
            const float* s = qkv + (size_t)row * QKV_N + col;
            float4 v;
            v.x = tfr(s[0]);
            v.y = tfr(s[(size_t)8 * QKV_N]);
            v.z = tfr(s[4]);
            v.w = tfr(s[(size_t)8 * QKV_N + 4]);
            qo[o] = v;
        }
        // K
        {
            int pr = (o >> 5) & 3, ks = (o >> 7) & 7;
            int key = tile * 64 + pr * 16 + lr;
            int d = h * 64 + ks * 8 + lc;
            const float* s = qkv + (size_t)key * QKV_N + EMB + d;
            float4 v;
            v.x = tfr(s[0]);
            v.y = tfr(s[4]);
            v.z = tfr(s[(size_t)8 * QKV_N]);
            v.w = tfr(s[(size_t)8 * QKV_N + 4]);
            ko[o] = v;
        }
        // V
        {
            int pr = (o >> 5) & 3, ks = (o >> 7) & 7;
            int vr = tile * 64 + ks * 8 + lc;
            int vd = h * 64 + pr * 16 + lr;
            const float* s = qkv + (size_t)vr * QKV_N + 2 * EMB + vd;
            float4 v;
            v.x = tfr(s[0]);
            v.y = tfr(s[(size_t)4 * QKV_N]);
            v.z = tfr(s[8]);
            v.w = tfr(s[(size_t)4 * QKV_N + 8]);
            vo[o] = v;
        }
    }
}

// ===========================================================================
// Packed tf32 GEMM: C[M,N] = A @ B (operands pre-packed fragment-major).
// 128x128x32 tile, 256 thr (8 warps 2x4), STG=3 cp.async pipeline.
// All fragment loads are conflict-free LDS.128; stage copies are linear.
// ===========================================================================
__global__ __launch_bounds__(256, 2) void pgemm(const float* __restrict__ Ap,
                                                const float* __restrict__ Bp,
                                                float* __restrict__ C,
                                                int M, int N, int K) {
    extern __shared__ float sm[];
    const int t    = threadIdx.x;
    const int w    = t >> 5;
    const int lane = t & 31;
    const int wm   = w >> 2;
    const int wn   = w & 3;
    const int lr   = lane >> 2;
    const int lc   = lane & 3;
    const int bx   = blockIdx.x;
    const int by   = blockIdx.y;
    const int KT   = K >> 5;

    float acc[4][4][4];
#pragma unroll
    for (int i = 0; i < 4; i++)
#pragma unroll
        for (int j = 0; j < 4; j++)
#pragma unroll
            for (int c = 0; c < 4; c++) acc[i][j][c] = 0.0f;

#define LOADK(s, kt)                                                            \
    {                                                                           \
        float* d = sm + (s) * STAGE_F;                                          \
        const float* ga = Ap + ((size_t)(by * KT + (kt))) * 4096;               \
        const float* gb = Bp + ((size_t)(bx * KT + (kt))) * 4096;               \
        _Pragma("unroll")                                                       \
        for (int i = 0; i < 4; i++) cp16(d + (t + 256 * i) * 4, ga + (t + 256 * i) * 4); \
        _Pragma("unroll")                                                       \
        for (int i = 0; i < 4; i++) cp16(d + 4096 + (t + 256 * i) * 4, gb + (t + 256 * i) * 4); \
        asm volatile("cp.async.commit_group;\n" ::: "memory");                  \
    }

    LOADK(0, 0);
    LOADK(1, 1);

    for (int kt = 0; kt < KT; kt++) {
        if (kt < KT - 1) asm volatile("cp.async.wait_group 1;\n" ::: "memory");
        else             asm volatile("cp.async.wait_group 0;\n" ::: "memory");
        __syncthreads();

        if (kt + 2 < KT) LOADK((kt + 2) % STG, kt + 2);

        const float* Asm = sm + (kt % STG) * STAGE_F;
        const float* Bsm = Asm + 4096;

#pragma unroll
        for (int ks = 0; ks < 4; ks++) {
            float4 a4[4];
#pragma unroll
            for (int mi = 0; mi < 4; mi++)
                a4[mi] = *(const float4*)&Asm[(((wm * 4 + ks) * 4 + mi) * 32 + lane) * 4];
            float4 b4[2];
#pragma unroll
            for (int hf = 0; hf < 2; hf++)
                b4[hf] = *(const float4*)&Bsm[(((wn * 4 + ks) * 2 + hf) * 32 + lane) * 4];

            uint32_t bf[4][2] = {
                {__float_as_uint(b4[0].x), __float_as_uint(b4[0].y)},
                {__float_as_uint(b4[0].z), __float_as_uint(b4[0].w)},
                {__float_as_uint(b4[1].x), __float_as_uint(b4[1].y)},
                {__float_as_uint(b4[1].z), __float_as_uint(b4[1].w)}};
#pragma unroll
            for (int mi = 0; mi < 4; mi++) {
                uint32_t af[4] = {__float_as_uint(a4[mi].x), __float_as_uint(a4[mi].y),
                                  __float_as_uint(a4[mi].z), __float_as_uint(a4[mi].w)};
#pragma unroll
                for (int ni = 0; ni < 4; ni++) mma_tf32(acc[mi][ni], af, bf[ni]);
            }
        }
        // no trailing sync needed: next iter's top sync precedes any overwrite
        // of the stage being read (STG=3).
    }

#pragma unroll
    for (int mi = 0; mi < 4; mi++) {
        const int r0 = by * 128 + wm * 64 + mi * 16 + lr;
#pragma unroll
        for (int ni = 0; ni < 4; ni++) {
            const int c0 = bx * 128 + wn * 32 + ni * 8 + 2 * lc;
            *(float2*)&C[(size_t)r0 * N + c0]       = make_float2(acc[mi][ni][0], acc[mi][ni][1]);
            *(float2*)&C[(size_t)(r0 + 8) * N + c0] = make_float2(acc[mi][ni][2], acc[mi][ni][3]);
        }
    }
#undef LOADK
}

// ===========================================================================
// Attention on packed Q/K/V: block=(64-query tile, head), 4 independent warps.
// No block-level syncs; K/V fragments via coalesced LDG.128 (L1-resident).
// ===========================================================================
__global__ __launch_bounds__(128) void attn_pk(const float* __restrict__ Qp,
                                               const float* __restrict__ Kp,
                                               const float* __restrict__ Vp,
                                               float* __restrict__ ctx) {
    __shared__ float Ps[64 * LQ];

    const int qb = blockIdx.x;
    const int h  = blockIdx.y;
    const int t  = threadIdx.x;
    const int w  = t >> 5;
    const int lane = t & 31;
    const int lr = lane >> 2;
    const int lc = lane & 3;
    const int q0 = qb * 64;

    // Q fragments -> registers (reused across all key tiles)
    const float4* q4 = (const float4*)(Qp + ((size_t)(h * NT64 + qb)) * 4096);
    float4 qf[8];
#pragma unroll
    for (int ks = 0; ks < 8; ks++) qf[ks] = q4[(w * 8 + ks) * 32 + lane];

    float o[8][4];
#pragma unroll
    for (int nt = 0; nt < 8; nt++)
#pragma unroll
        for (int c = 0; c < 4; c++) o[nt][c] = 0.0f;
    float m[2] = {-1e30f, -1e30f};
    float l[2] = {0.0f, 0.0f};

    const int ktlo = (qb >= 4) ? qb - 4 : 0;
    for (int kt = ktlo; kt <= qb; kt++) {
        const int k0 = kt * 64;
        const float4* kp4 = (const float4*)(Kp + ((size_t)(h * NT64 + kt)) * 4096);
        const float4* vp4 = (const float4*)(Vp + ((size_t)(h * NT64 + kt)) * 4096);

        // S = Q K^T
        float acc[8][4];
#pragma unroll
        for (int nt = 0; nt < 8; nt++)
#pragma unroll
            for (int c = 0; c < 4; c++) acc[nt][c] = 0.0f;

#pragma unroll
        for (int ks = 0; ks < 8; ks++) {
            uint32_t af[4] = {__float_as_uint(qf[ks].x), __float_as_uint(qf[ks].y),
                              __float_as_uint(qf[ks].z), __float_as_uint(qf[ks].w)};
#pragma unroll
            for (int pr = 0; pr < 4; pr++) {
                float4 kv = kp4[(ks * 4 + pr) * 32 + lane];
                uint32_t b0[2] = {__float_as_uint(kv.x), __float_as_uint(kv.y)};
                uint32_t b1[2] = {__float_as_uint(kv.z), __float_as_uint(kv.w)};
                mma_tf32(acc[2 * pr], af, b0);
                mma_tf32(acc[2 * pr + 1], af, b1);
            }
        }

        // masked online softmax: 2 rows per thread
#pragma unroll
        for (int i = 0; i < 2; i++) {
            const int qi = q0 + 16 * w + lr + 8 * i;
            float sv[16];
            float mt = -1e30f;
#pragma unroll
            for (int nt = 0; nt < 8; nt++) {
#pragma unroll
                for (int c = 0; c < 2; c++) {
                    int kj = k0 + 8 * nt + 2 * lc + c;
                    bool ok = (kj <= qi) && (kj > qi - WIN);
                    float s = acc[nt][2 * i + c] * 0.125f;
                    sv[nt * 2 + c] = ok ? s : -1e30f;
                    mt = fmaxf(mt, sv[nt * 2 + c]);
                }
            }
            mt = fmaxf(mt, __shfl_xor_sync(0xffffffffu, mt, 1));
            mt = fmaxf(mt, __shfl_xor_sync(0xffffffffu, mt, 2));

            float alpha = 1.0f;
            if (mt > m[i]) { alpha = __expf(m[i] - mt); m[i] = mt; }

            float ls = 0.0f;
            float p[16];
#pragma unroll
            for (int j = 0; j < 16; j++) {
                p[j] = (sv[j] > -1e29f) ? __expf(sv[j] - m[i]) : 0.0f;
                ls += p[j];
            }
            ls += __shfl_xor_sync(0xffffffffu, ls, 1);
            ls += __shfl_xor_sync(0xffffffffu, ls, 2);

            l[i] = l[i] * alpha + ls;
#pragma unroll
            for (int nt = 0; nt < 8; nt++) {
                o[nt][2 * i]     *= alpha;
                o[nt][2 * i + 1] *= alpha;
                float2 pr2 = make_float2(tfr(p[nt * 2]), tfr(p[nt * 2 + 1]));
                *(float2*)&Ps[(16 * w + lr + 8 * i) * LQ + 8 * nt + 2 * lc] = pr2;
            }
        }
        __syncwarp();

        // O += P V
#pragma unroll
        for (int ks = 0; ks < 8; ks++) {
            const float* pp = &Ps[(16 * w + lr) * LQ + 8 * ks + lc];
            uint32_t pa[4] = {__float_as_uint(pp[0]), __float_as_uint(pp[8 * LQ]),
                              __float_as_uint(pp[4]), __float_as_uint(pp[8 * LQ + 4])};
#pragma unroll
            for (int pr = 0; pr < 4; pr++) {
                float4 vv = vp4[(ks * 4 + pr) * 32 + lane];
                uint32_t b0[2] = {__float_as_uint(vv.x), __float_as_uint(vv.y)};
                uint32_t b1[2] = {__float_as_uint(vv.z), __float_as_uint(vv.w)};
                mma_tf32(o[2 * pr], pa, b0);
                mma_tf32(o[2 * pr + 1], pa, b1);
            }
        }
        __syncwarp();
    }

    // epilogue: normalize, plain fp32 ctx (pack_a(ctx) rounds later)
    const float inv0 = 1.0f / l[0];
    const float inv1 = 1.0f / l[1];
    const int row0 = q0 + 16 * w + lr;
    const int col0 = h * HD;
#pragma unroll
    for (int nt = 0; nt < 8; nt++) {
        int c0 = col0 + 8 * nt + 2 * lc;
        *(float2*)&ctx[(size_t)row0 * EMB + c0] =
            make_float2(o[nt][0] * inv0, o[nt][1] * inv0);
        *(float2*)&ctx[(size_t)(row0 + 8) * EMB + c0] =
            make_float2(o[nt][2] * inv1, o[nt][3] * inv1);
    }
}

// ===========================================================================
extern "C" void kernel_launch(void* const* d_in, const int* in_sizes, int n_in,
                              void* d_out, int out_size) {
    const float* x     = (const float*)d_in[0];
    const float* w_qkv = (const float*)d_in[2];
    const float* w_out = (const float*)d_in[3];
    float* out = (float*)d_out;

    float *qkv, *ctx, *xap, *cxp, *wqp, *wop, *qpk, *kpk, *vpk;
    cudaGetSymbolAddress((void**)&qkv, g_qkv);
    cudaGetSymbolAddress((void**)&ctx, g_ctx);
    cudaGetSymbolAddress((void**)&xap, g_xap);
    cudaGetSymbolAddress((void**)&cxp, g_cxp);
    cudaGetSymbolAddress((void**)&wqp, g_wqp);
    cudaGetSymbolAddress((void**)&wop, g_wop);
    cudaGetSymbolAddress((void**)&qpk, g_qpk);
    cudaGetSymbolAddress((void**)&kpk, g_kpk);
    cudaGetSymbolAddress((void**)&vpk, g_vpk);

    cudaFuncSetAttribute(pgemm, cudaFuncAttributeMaxDynamicSharedMemorySize, GEMM_SMEM);

    // 0) pre-pack operands (tf32-rounded, fragment-major)
    pack_b<<<dim3(EMB / 32, QKV_N / 128), 256>>>(w_qkv, wqp, EMB, QKV_N);
    pack_b<<<dim3(EMB / 32, EMB / 128), 256>>>(w_out, wop, EMB, EMB);
    pack_a<<<dim3(EMB / 32, SEQ / 128), 256>>>(x, xap, EMB);

    // 1) qkv = x @ w_qkv
    pgemm<<<dim3(QKV_N / 128, SEQ / 128), 256, GEMM_SMEM>>>(xap, wqp, qkv, SEQ, QKV_N, EMB);

    // 2) pack q/k/v per (head, tile), then attention
    pack_qkv<<<dim3(NT64, NH), 256>>>(qkv, qpk, kpk, vpk);
    attn_pk<<<dim3(NT64, NH), 128>>>(qpk, kpk, vpk, ctx);

    // 3) out = ctx @ w_out
    pack_a<<<dim3(EMB / 32, SEQ / 128), 256>>>(ctx, cxp, EMB);
    pgemm<<<dim3(EMB / 128, SEQ / 128), 256, GEMM_SMEM>>>(cxp, wop, out, SEQ, EMB, EMB);
}